// round 16
// baseline (speedup 1.0000x reference)
#include <cuda_runtime.h>
#include <cuda_bf16.h>
#include <cstdint>

#define N_NODES 50000
#define DIM     256
#define NE      300000
#define NL      5
#define BN_EPS  1e-5f

#define BM 128
#define BN 128
#define BK 16
#define SSTRIDE 136
#define NBLK_SCAN ((N_NODES + 1023) / 1024)   // 49

// ---------------- scratch (static device globals; no runtime allocation) -----
__device__ float g_z[(size_t)N_NODES * DIM];
__device__ float g_y[(size_t)N_NODES * DIM];
__device__ float g_v[(size_t)N_NODES * DIM];
__device__ float g_stats[NL * 2 * 512];
__device__ float g_ss2[2 * DIM];
__device__ int   g_adj[NE];
__device__ int   g_off[N_NODES + 1];
__device__ int   g_cur[N_NODES];
__device__ int   g_bsum[NBLK_SCAN];

// ---------------- helpers ----------------------------------------------------
__device__ __forceinline__ void split_bf16x2(float x0, float x1, uint32_t& hi, uint32_t& lo) {
    uint32_t h;
    asm("cvt.rn.bf16x2.f32 %0, %1, %2;" : "=r"(h) : "f"(x1), "f"(x0));
    float h0 = __uint_as_float(h << 16);
    float h1 = __uint_as_float(h & 0xffff0000u);
    asm("cvt.rn.bf16x2.f32 %0, %1, %2;" : "=r"(lo) : "f"(x1 - h1), "f"(x0 - h0));
    hi = h;
}
__device__ __forceinline__ void mma_bf16(float* d, const uint32_t* a, const uint32_t* b) {
    asm volatile(
        "mma.sync.aligned.m16n8k16.row.col.f32.bf16.bf16.f32 "
        "{%0,%1,%2,%3}, {%4,%5,%6,%7}, {%8,%9}, {%0,%1,%2,%3};"
        : "+f"(d[0]), "+f"(d[1]), "+f"(d[2]), "+f"(d[3])
        : "r"(a[0]), "r"(a[1]), "r"(a[2]), "r"(a[3]), "r"(b[0]), "r"(b[1]));
}
__device__ __forceinline__ void bn_ss(int slot, int c, const float* __restrict__ gamma,
                                      const float* __restrict__ beta,
                                      float& sc, float& sh) {
    float s = g_stats[slot * 512 + c];
    float q = g_stats[slot * 512 + 256 + c];
    float mean = s * (1.0f / N_NODES);
    float var  = q * (1.0f / N_NODES) - mean * mean;
    float istd = rsqrtf(var + BN_EPS);
    sc = gamma[c] * istd;
    sh = beta[c] - mean * sc;
}

// ---------------- init: zero stats + degree cursors (fused) ------------------
__global__ void k_zero_init() {
    int i = blockIdx.x * 256 + threadIdx.x;
    if (i < NL * 2 * 512) g_stats[i] = 0.0f;
    if (i < N_NODES) g_cur[i] = 0;
}

// ---------------- CSR build (once per launch) --------------------------------
__global__ void k_hist(const int* __restrict__ dst) {
    int e = blockIdx.x * 256 + threadIdx.x;
    if (e < NE) atomicAdd(&g_cur[dst[e]], 1);
}
__global__ void k_scan1() {
    __shared__ int warpsum[32];
    const int lane = threadIdx.x & 31;
    const int wid  = threadIdx.x >> 5;
    const int i    = blockIdx.x * 1024 + threadIdx.x;
    int v = (i < N_NODES) ? g_cur[i] : 0;

    int s = v;
#pragma unroll
    for (int o = 1; o < 32; o <<= 1) {
        int t = __shfl_up_sync(0xffffffffu, s, o);
        if (lane >= o) s += t;
    }
    if (lane == 31) warpsum[wid] = s;
    __syncthreads();
    if (wid == 0) {
        int ws = warpsum[lane];
#pragma unroll
        for (int o = 1; o < 32; o <<= 1) {
            int t = __shfl_up_sync(0xffffffffu, ws, o);
            if (lane >= o) ws += t;
        }
        warpsum[lane] = ws;
    }
    __syncthreads();
    int base = (wid > 0) ? warpsum[wid - 1] : 0;
    if (i < N_NODES) g_off[i] = base + s - v;
    if (threadIdx.x == 0) g_bsum[blockIdx.x] = warpsum[31];
}
__global__ void k_scan2() {
    if (threadIdx.x == 0) {
        int run = 0;
        for (int b = 0; b < NBLK_SCAN; b++) {
            int v = g_bsum[b];
            g_bsum[b] = run;
            run += v;
        }
    }
}
__global__ void k_scan3() {
    const int i = blockIdx.x * 1024 + threadIdx.x;
    if (i < N_NODES) {
        int o = g_off[i] + g_bsum[blockIdx.x];
        g_off[i] = o;
        g_cur[i] = o;
    }
    if (i == 0) g_off[N_NODES] = NE;
}
__global__ void k_fill(const int* __restrict__ src, const int* __restrict__ dst) {
    int e = blockIdx.x * 256 + threadIdx.x;
    if (e >= NE) return;
    int pos = atomicAdd(&g_cur[dst[e]], 1);
    g_adj[pos] = src[e];
}

// ---------------- fused gather + BN2-apply + eps-init -------------------------
// zout[d] = (1+eps[l]) * self(zin[d]) + sum_{s in N(d)} msg(zin[s])
template <bool TRANSFORM>
__global__ __launch_bounds__(256)
void k_gather(const float* __restrict__ zin, float* __restrict__ zout,
              const float* __restrict__ eps, int l,
              int slotIn, const float* __restrict__ gamma, const float* __restrict__ beta) {
    __shared__ float ssm[2 * DIM];
    const int tid  = threadIdx.x;
    const int lane = tid & 31;
    const int node = blockIdx.x * 8 + (tid >> 5);

    if (TRANSFORM) {
        if (tid < DIM) {
            float sc, sh;
            bn_ss(slotIn, tid, gamma, beta, sc, sh);
            ssm[tid] = sc;
            ssm[DIM + tid] = sh;
        }
        __syncthreads();
    }
    if (node >= N_NODES) return;

    const int c0 = lane * 4;
    float4 sc0, sh0, sc1, sh1;
    if (TRANSFORM) {
        sc0 = *(const float4*)(ssm + c0);
        sc1 = *(const float4*)(ssm + 128 + c0);
        sh0 = *(const float4*)(ssm + DIM + c0);
        sh1 = *(const float4*)(ssm + DIM + 128 + c0);
    }

    auto t4 = [&](float4 v, const float4& sc, const float4& sh) {
        if (TRANSFORM) {
            v.x = fmaxf(fmaf(v.x, sc.x, sh.x), 0.0f);
            v.y = fmaxf(fmaf(v.y, sc.y, sh.y), 0.0f);
            v.z = fmaxf(fmaf(v.z, sc.z, sh.z), 0.0f);
            v.w = fmaxf(fmaf(v.w, sc.w, sh.w), 0.0f);
        }
        return v;
    };

    const float* zr = zin + (size_t)node * DIM;
    float a = 1.0f + eps[l];
    float4 s0 = t4(*(const float4*)(zr + c0),       sc0, sh0);
    float4 s1 = t4(*(const float4*)(zr + 128 + c0), sc1, sh1);
    float4 acc0 = make_float4(a * s0.x, a * s0.y, a * s0.z, a * s0.w);
    float4 acc1 = make_float4(a * s1.x, a * s1.y, a * s1.z, a * s1.w);

    const int beg = g_off[node], end = g_off[node + 1];
    for (int j = beg; j < end; j++) {
        const float* sr = zin + (size_t)g_adj[j] * DIM;
        float4 m0 = t4(*(const float4*)(sr + c0),       sc0, sh0);
        float4 m1 = t4(*(const float4*)(sr + 128 + c0), sc1, sh1);
        if (!TRANSFORM) {
            m0.x = fmaxf(m0.x, 0.f); m0.y = fmaxf(m0.y, 0.f);
            m0.z = fmaxf(m0.z, 0.f); m0.w = fmaxf(m0.w, 0.f);
            m1.x = fmaxf(m1.x, 0.f); m1.y = fmaxf(m1.y, 0.f);
            m1.z = fmaxf(m1.z, 0.f); m1.w = fmaxf(m1.w, 0.f);
        }
        acc0.x += m0.x; acc0.y += m0.y; acc0.z += m0.z; acc0.w += m0.w;
        acc1.x += m1.x; acc1.y += m1.y; acc1.z += m1.z; acc1.w += m1.w;
    }

    float* zo = zout + (size_t)node * DIM;
    *(float4*)(zo + c0)       = acc0;
    *(float4*)(zo + 128 + c0) = acc1;
}

// ---------------- 3xBF16 GEMM, double-buffered, BN-ss prologue ---------------
// Epilogue stats: butterfly-reduced over g-lanes, direct global atomics.
template <bool TRANSFORM_A>
__global__ __launch_bounds__(256, 2)
void k_gemm(const float* __restrict__ A, const float* __restrict__ W,
            const float* __restrict__ bias, float* __restrict__ C,
            int slotIn, const float* __restrict__ gamma, const float* __restrict__ beta,
            int slotOut) {
    __shared__ uint32_t As_hi[2][8][SSTRIDE];
    __shared__ uint32_t As_lo[2][8][SSTRIDE];
    __shared__ uint32_t Bs_hi[2][8][SSTRIDE];
    __shared__ uint32_t Bs_lo[2][8][SSTRIDE];
    __shared__ float ssm[2 * DIM];

    const int tid  = threadIdx.x;
    const int lane = tid & 31;
    const int warp = tid >> 5;
    const int wr   = warp >> 2;
    const int wc   = warp & 3;
    const int g    = lane >> 2;
    const int t    = lane & 3;

    const int rowBase = blockIdx.y * BM;
    const int colBase = blockIdx.x * BN;

    if (TRANSFORM_A) {
        if (tid < DIM) {
            float sc, sh;
            bn_ss(slotIn, tid, gamma, beta, sc, sh);
            ssm[tid] = sc;
            ssm[DIM + tid] = sh;
        }
        __syncthreads();
    }

    const int arow = tid >> 1;
    const int ak   = (tid & 1) * 4;
    const int bk2  = (tid >> 5) * 2;
    const int bkp  = tid >> 5;
    const int bcol = (tid & 31) * 4;

    const int agrow = rowBase + arow;
    const bool a_ok = (agrow < N_NODES);
    const float* Arow = A + (size_t)agrow * DIM;

    float acc[4][4][4];
#pragma unroll
    for (int mt = 0; mt < 4; mt++)
#pragma unroll
        for (int nt = 0; nt < 4; nt++)
#pragma unroll
            for (int j = 0; j < 4; j++) acc[mt][nt][j] = 0.0f;

    float4 av0, av1, br0, br1;

    auto fetch = [&](int k0) {
        av0 = make_float4(0.f, 0.f, 0.f, 0.f);
        av1 = make_float4(0.f, 0.f, 0.f, 0.f);
        if (a_ok) {
            av0 = *(const float4*)(Arow + k0 + ak);
            av1 = *(const float4*)(Arow + k0 + ak + 8);
        }
        if (TRANSFORM_A) {
            int kc0 = k0 + ak, kc1 = k0 + ak + 8;
            av0.x = fmaxf(fmaf(av0.x, ssm[kc0 + 0], ssm[DIM + kc0 + 0]), 0.0f);
            av0.y = fmaxf(fmaf(av0.y, ssm[kc0 + 1], ssm[DIM + kc0 + 1]), 0.0f);
            av0.z = fmaxf(fmaf(av0.z, ssm[kc0 + 2], ssm[DIM + kc0 + 2]), 0.0f);
            av0.w = fmaxf(fmaf(av0.w, ssm[kc0 + 3], ssm[DIM + kc0 + 3]), 0.0f);
            av1.x = fmaxf(fmaf(av1.x, ssm[kc1 + 0], ssm[DIM + kc1 + 0]), 0.0f);
            av1.y = fmaxf(fmaf(av1.y, ssm[kc1 + 1], ssm[DIM + kc1 + 1]), 0.0f);
            av1.z = fmaxf(fmaf(av1.z, ssm[kc1 + 2], ssm[DIM + kc1 + 2]), 0.0f);
            av1.w = fmaxf(fmaf(av1.w, ssm[kc1 + 3], ssm[DIM + kc1 + 3]), 0.0f);
        }
        br0 = *(const float4*)(W + (size_t)(k0 + bk2)     * DIM + colBase + bcol);
        br1 = *(const float4*)(W + (size_t)(k0 + bk2 + 1) * DIM + colBase + bcol);
    };

    auto stash = [&](int buf) {
        uint32_t hi, lo;
        int kp = ak >> 1;
        split_bf16x2(av0.x, av0.y, hi, lo);
        As_hi[buf][kp][arow] = hi;     As_lo[buf][kp][arow] = lo;
        split_bf16x2(av0.z, av0.w, hi, lo);
        As_hi[buf][kp + 1][arow] = hi; As_lo[buf][kp + 1][arow] = lo;
        split_bf16x2(av1.x, av1.y, hi, lo);
        As_hi[buf][kp + 4][arow] = hi; As_lo[buf][kp + 4][arow] = lo;
        split_bf16x2(av1.z, av1.w, hi, lo);
        As_hi[buf][kp + 5][arow] = hi; As_lo[buf][kp + 5][arow] = lo;
        {
            uint32_t ph[4], pl[4];
            split_bf16x2(br0.x, br1.x, ph[0], pl[0]);
            split_bf16x2(br0.y, br1.y, ph[1], pl[1]);
            split_bf16x2(br0.z, br1.z, ph[2], pl[2]);
            split_bf16x2(br0.w, br1.w, ph[3], pl[3]);
            *(uint4*)&Bs_hi[buf][bkp][bcol] = *(uint4*)ph;
            *(uint4*)&Bs_lo[buf][bkp][bcol] = *(uint4*)pl;
        }
    };

    const int mrow = wr * 64;
    const int ncol = wc * 32;

    fetch(0);
    stash(0);
    __syncthreads();

#pragma unroll 2
    for (int it = 0; it < DIM / BK; it++) {
        const int cur = it & 1;
        if (it < DIM / BK - 1) fetch((it + 1) * BK);

        uint32_t ahi[4][4], bhi[4][2], blo[4][2];
#pragma unroll
        for (int mt = 0; mt < 4; mt++) {
            int r = mrow + mt * 16 + g;
            ahi[mt][0] = As_hi[cur][t][r];
            ahi[mt][1] = As_hi[cur][t][r + 8];
            ahi[mt][2] = As_hi[cur][t + 4][r];
            ahi[mt][3] = As_hi[cur][t + 4][r + 8];
        }
#pragma unroll
        for (int nt = 0; nt < 4; nt++) {
            int c = ncol + nt * 8 + g;
            bhi[nt][0] = Bs_hi[cur][t][c];
            bhi[nt][1] = Bs_hi[cur][t + 4][c];
            blo[nt][0] = Bs_lo[cur][t][c];
            blo[nt][1] = Bs_lo[cur][t + 4][c];
        }
#pragma unroll
        for (int mt = 0; mt < 4; mt++)
#pragma unroll
            for (int nt = 0; nt < 4; nt++)
                mma_bf16(acc[mt][nt], ahi[mt], bhi[nt]);
#pragma unroll
        for (int mt = 0; mt < 4; mt++)
#pragma unroll
            for (int nt = 0; nt < 4; nt++)
                mma_bf16(acc[mt][nt], ahi[mt], blo[nt]);
        uint32_t alo[4][4];
#pragma unroll
        for (int mt = 0; mt < 4; mt++) {
            int r = mrow + mt * 16 + g;
            alo[mt][0] = As_lo[cur][t][r];
            alo[mt][1] = As_lo[cur][t][r + 8];
            alo[mt][2] = As_lo[cur][t + 4][r];
            alo[mt][3] = As_lo[cur][t + 4][r + 8];
        }
#pragma unroll
        for (int mt = 0; mt < 4; mt++)
#pragma unroll
            for (int nt = 0; nt < 4; nt++)
                mma_bf16(acc[mt][nt], alo[mt], bhi[nt]);

        if (it < DIM / BK - 1) {
            stash(cur ^ 1);
            __syncthreads();
        }
    }

    // ---- epilogue: bias, store; stats via g-lane butterfly + global atomics ----
    float bs[4][2];
#pragma unroll
    for (int nt = 0; nt < 4; nt++) {
        int c = colBase + ncol + nt * 8 + 2 * t;
        bs[nt][0] = bias[c];
        bs[nt][1] = bias[c + 1];
    }

    float csum[4][2], csq[4][2];
#pragma unroll
    for (int nt = 0; nt < 4; nt++) {
        csum[nt][0] = 0.f; csum[nt][1] = 0.f;
        csq[nt][0] = 0.f;  csq[nt][1] = 0.f;
    }

#pragma unroll
    for (int mt = 0; mt < 4; mt++) {
        int r0 = rowBase + mrow + mt * 16 + g;
        int r1 = r0 + 8;
        bool ok0 = (r0 < N_NODES), ok1 = (r1 < N_NODES);
#pragma unroll
        for (int nt = 0; nt < 4; nt++) {
            int c = colBase + ncol + nt * 8 + 2 * t;
            float v0 = acc[mt][nt][0] + bs[nt][0];
            float v1 = acc[mt][nt][1] + bs[nt][1];
            float v2 = acc[mt][nt][2] + bs[nt][0];
            float v3 = acc[mt][nt][3] + bs[nt][1];
            if (ok0) {
                *(float2*)(C + (size_t)r0 * DIM + c) = make_float2(v0, v1);
                csum[nt][0] += v0; csq[nt][0] += v0 * v0;
                csum[nt][1] += v1; csq[nt][1] += v1 * v1;
            }
            if (ok1) {
                *(float2*)(C + (size_t)r1 * DIM + c) = make_float2(v2, v3);
                csum[nt][0] += v2; csq[nt][0] += v2 * v2;
                csum[nt][1] += v3; csq[nt][1] += v3 * v3;
            }
        }
    }
    // lanes with the same t (g = 0..7) hold identical columns: reduce over
    // lane bits 2..4, then only g==0 lanes hit global memory.
#pragma unroll
    for (int nt = 0; nt < 4; nt++) {
#pragma unroll
        for (int k = 0; k < 2; k++) {
#pragma unroll
            for (int o = 4; o <= 16; o <<= 1) {
                csum[nt][k] += __shfl_xor_sync(0xffffffffu, csum[nt][k], o);
                csq[nt][k]  += __shfl_xor_sync(0xffffffffu, csq[nt][k],  o);
            }
        }
    }
    if (g == 0) {
#pragma unroll
        for (int nt = 0; nt < 4; nt++) {
            int c = colBase + ncol + nt * 8 + 2 * t;
            atomicAdd(&g_stats[slotOut * 512 +       c],     csum[nt][0]);
            atomicAdd(&g_stats[slotOut * 512 + 256 + c],     csq[nt][0]);
            atomicAdd(&g_stats[slotOut * 512 +       c + 1], csum[nt][1]);
            atomicAdd(&g_stats[slotOut * 512 + 256 + c + 1], csq[nt][1]);
        }
    }
}

// last layer's BN2 -> g_ss2 for k_out
__global__ void k_finalize(int slot, const float* __restrict__ gamma,
                           const float* __restrict__ beta) {
    int c = threadIdx.x;
    if (c >= DIM) return;
    float sc, sh;
    bn_ss(slot, c, gamma, beta, sc, sh);
    g_ss2[c]       = sc;
    g_ss2[DIM + c] = sh;
}

// final output: out = ss2 * v + shift  (no relu, layer L-1)
__global__ void k_out(const float* __restrict__ vin, float* __restrict__ out) {
    long i = (long)blockIdx.x * 256 + threadIdx.x;
    const long tot = (long)N_NODES * DIM / 4;
    if (i >= tot) return;
    int c = (int)(i & 63) << 2;
    float4 v = ((const float4*)vin)[i];
    v.x = fmaf(v.x, g_ss2[c + 0], g_ss2[DIM + c + 0]);
    v.y = fmaf(v.y, g_ss2[c + 1], g_ss2[DIM + c + 1]);
    v.z = fmaf(v.z, g_ss2[c + 2], g_ss2[DIM + c + 2]);
    v.w = fmaf(v.w, g_ss2[c + 3], g_ss2[DIM + c + 3]);
    ((float4*)out)[i] = v;
}

// ---------------- host-side orchestration ------------------------------------
extern "C" void kernel_launch(void* const* d_in, const int* in_sizes, int n_in,
                              void* d_out, int out_size) {
    const float* x    = (const float*)d_in[0];
    const int*   src  = (const int*)  d_in[1];
    const int*   dst  = (const int*)  d_in[2];
    const float* W1   = (const float*)d_in[3];
    const float* b1   = (const float*)d_in[4];
    const float* g1   = (const float*)d_in[5];
    const float* bt1  = (const float*)d_in[6];
    const float* W2   = (const float*)d_in[7];
    const float* b2   = (const float*)d_in[8];
    const float* eps  = (const float*)d_in[9];
    const float* bn_g = (const float*)d_in[10];
    const float* bn_b = (const float*)d_in[11];
    float* out = (float*)d_out;

    float *zp, *yp, *vp;
    cudaGetSymbolAddress((void**)&zp, g_z);
    cudaGetSymbolAddress((void**)&yp, g_y);
    cudaGetSymbolAddress((void**)&vp, g_v);

    const long ew_items = (long)N_NODES * DIM / 4;
    const int  ew_grid  = (int)((ew_items + 255) / 256);
    const dim3 gemm_grid(DIM / BN, (N_NODES + BM - 1) / BM);   // (2, 391)
    const int  gat_grid = (N_NODES + 7) / 8;                   // 6250

    // ---- init + CSR build (once per launch) ----
    k_zero_init<<<(N_NODES + 255) / 256, 256>>>();
    k_hist<<<(NE + 255) / 256, 256>>>(dst);
    k_scan1<<<NBLK_SCAN, 1024>>>();
    k_scan2<<<1, 32>>>();
    k_scan3<<<NBLK_SCAN, 1024>>>();
    k_fill<<<(NE + 255) / 256, 256>>>(src, dst);

    for (int l = 0; l < NL; l++) {
        if (l == 0)
            k_gather<false><<<gat_grid, 256>>>(x, zp, eps, 0, 0, nullptr, nullptr);
        else
            k_gather<true><<<gat_grid, 256>>>(vp, zp, eps, l,
                                              (l - 1) * 2 + 1,
                                              bn_g + (size_t)(l - 1) * DIM,
                                              bn_b + (size_t)(l - 1) * DIM);

        k_gemm<false><<<gemm_grid, 256>>>(zp, W1 + (size_t)l * DIM * DIM,
                                          b1 + (size_t)l * DIM, yp,
                                          0, nullptr, nullptr, l * 2);

        k_gemm<true><<<gemm_grid, 256>>>(yp, W2 + (size_t)l * DIM * DIM,
                                         b2 + (size_t)l * DIM, vp,
                                         l * 2,
                                         g1 + (size_t)l * DIM,
                                         bt1 + (size_t)l * DIM,
                                         l * 2 + 1);
    }

    k_finalize<<<1, 256>>>((NL - 1) * 2 + 1,
                           bn_g + (size_t)(NL - 1) * DIM,
                           bn_b + (size_t)(NL - 1) * DIM);
    k_out<<<ew_grid, 256>>>(vp, out);
}

// round 17
// speedup vs baseline: 1.1805x; 1.1805x over previous
#include <cuda_runtime.h>
#include <cuda_bf16.h>
#include <cstdint>

#define N_NODES 50000
#define DIM     256
#define NE      300000
#define NL      5
#define BN_EPS  1e-5f

#define BM 128
#define BN 128
#define BK 16
#define SSTRIDE 136
#define NBLK_SCAN ((N_NODES + 1023) / 1024)   // 49

// ---------------- scratch (static device globals; no runtime allocation) -----
__device__ float g_z[(size_t)N_NODES * DIM];
__device__ float g_y[(size_t)N_NODES * DIM];
__device__ float g_v[(size_t)N_NODES * DIM];
__device__ float g_stats[NL * 2 * 512];
__device__ float g_ss2[2 * DIM];
__device__ int   g_adj[NE];
__device__ int   g_off[N_NODES + 1];
__device__ int   g_cur[N_NODES];
__device__ int   g_bsum[NBLK_SCAN];

// ---------------- helpers ----------------------------------------------------
__device__ __forceinline__ void split_bf16x2(float x0, float x1, uint32_t& hi, uint32_t& lo) {
    uint32_t h;
    asm("cvt.rn.bf16x2.f32 %0, %1, %2;" : "=r"(h) : "f"(x1), "f"(x0));
    float h0 = __uint_as_float(h << 16);
    float h1 = __uint_as_float(h & 0xffff0000u);
    asm("cvt.rn.bf16x2.f32 %0, %1, %2;" : "=r"(lo) : "f"(x1 - h1), "f"(x0 - h0));
    hi = h;
}
__device__ __forceinline__ void mma_bf16(float* d, const uint32_t* a, const uint32_t* b) {
    asm volatile(
        "mma.sync.aligned.m16n8k16.row.col.f32.bf16.bf16.f32 "
        "{%0,%1,%2,%3}, {%4,%5,%6,%7}, {%8,%9}, {%0,%1,%2,%3};"
        : "+f"(d[0]), "+f"(d[1]), "+f"(d[2]), "+f"(d[3])
        : "r"(a[0]), "r"(a[1]), "r"(a[2]), "r"(a[3]), "r"(b[0]), "r"(b[1]));
}
__device__ __forceinline__ void bn_ss(int slot, int c, const float* __restrict__ gamma,
                                      const float* __restrict__ beta,
                                      float& sc, float& sh) {
    float s = g_stats[slot * 512 + c];
    float q = g_stats[slot * 512 + 256 + c];
    float mean = s * (1.0f / N_NODES);
    float var  = q * (1.0f / N_NODES) - mean * mean;
    float istd = rsqrtf(var + BN_EPS);
    sc = gamma[c] * istd;
    sh = beta[c] - mean * sc;
}

// ---------------- init: zero stats + degree cursors (fused) ------------------
__global__ void k_zero_init() {
    int i = blockIdx.x * 256 + threadIdx.x;
    if (i < NL * 2 * 512) g_stats[i] = 0.0f;
    if (i < N_NODES) g_cur[i] = 0;
}

// ---------------- CSR build (once per launch) --------------------------------
__global__ void k_hist(const int* __restrict__ dst) {
    int e = blockIdx.x * 256 + threadIdx.x;
    if (e < NE) atomicAdd(&g_cur[dst[e]], 1);
}
// phase 1: per-block warp-shuffle scan; local exclusive -> g_off, totals -> g_bsum
__global__ void k_scan1() {
    __shared__ int warpsum[32];
    const int lane = threadIdx.x & 31;
    const int wid  = threadIdx.x >> 5;
    const int i    = blockIdx.x * 1024 + threadIdx.x;
    int v = (i < N_NODES) ? g_cur[i] : 0;

    int s = v;
#pragma unroll
    for (int o = 1; o < 32; o <<= 1) {
        int t = __shfl_up_sync(0xffffffffu, s, o);
        if (lane >= o) s += t;
    }
    if (lane == 31) warpsum[wid] = s;
    __syncthreads();
    if (wid == 0) {
        int ws = warpsum[lane];
#pragma unroll
        for (int o = 1; o < 32; o <<= 1) {
            int t = __shfl_up_sync(0xffffffffu, ws, o);
            if (lane >= o) ws += t;
        }
        warpsum[lane] = ws;
    }
    __syncthreads();
    int base = (wid > 0) ? warpsum[wid - 1] : 0;
    if (i < N_NODES) g_off[i] = base + s - v;
    if (threadIdx.x == 0) g_bsum[blockIdx.x] = warpsum[31];
}
// phase 2 (fused): thread 0 of each block sums preceding block totals (<=48
// L2-hit int loads, hidden under the block's own global traffic)
__global__ void k_scan3() {
    __shared__ int base_sh;
    if (threadIdx.x == 0) {
        int run = 0;
        for (int b = 0; b < blockIdx.x; b++) run += g_bsum[b];
        base_sh = run;
    }
    __syncthreads();
    const int i = blockIdx.x * 1024 + threadIdx.x;
    if (i < N_NODES) {
        int o = g_off[i] + base_sh;
        g_off[i] = o;
        g_cur[i] = o;
    }
    if (i == 0) g_off[N_NODES] = NE;
}
__global__ void k_fill(const int* __restrict__ src, const int* __restrict__ dst) {
    int e = blockIdx.x * 256 + threadIdx.x;
    if (e >= NE) return;
    int pos = atomicAdd(&g_cur[dst[e]], 1);
    g_adj[pos] = src[e];
}

// ---------------- fused gather + BN2-apply + eps-init -------------------------
// zout[d] = (1+eps[l]) * self(zin[d]) + sum_{s in N(d)} msg(zin[s])
template <bool TRANSFORM>
__global__ __launch_bounds__(256)
void k_gather(const float* __restrict__ zin, float* __restrict__ zout,
              const float* __restrict__ eps, int l,
              int slotIn, const float* __restrict__ gamma, const float* __restrict__ beta) {
    __shared__ float ssm[2 * DIM];
    const int tid  = threadIdx.x;
    const int lane = tid & 31;
    const int node = blockIdx.x * 8 + (tid >> 5);

    if (TRANSFORM) {
        if (tid < DIM) {
            float sc, sh;
            bn_ss(slotIn, tid, gamma, beta, sc, sh);
            ssm[tid] = sc;
            ssm[DIM + tid] = sh;
        }
        __syncthreads();
    }
    if (node >= N_NODES) return;

    const int c0 = lane * 4;
    float4 sc0, sh0, sc1, sh1;
    if (TRANSFORM) {
        sc0 = *(const float4*)(ssm + c0);
        sc1 = *(const float4*)(ssm + 128 + c0);
        sh0 = *(const float4*)(ssm + DIM + c0);
        sh1 = *(const float4*)(ssm + DIM + 128 + c0);
    }

    auto t4 = [&](float4 v, const float4& sc, const float4& sh) {
        if (TRANSFORM) {
            v.x = fmaxf(fmaf(v.x, sc.x, sh.x), 0.0f);
            v.y = fmaxf(fmaf(v.y, sc.y, sh.y), 0.0f);
            v.z = fmaxf(fmaf(v.z, sc.z, sh.z), 0.0f);
            v.w = fmaxf(fmaf(v.w, sc.w, sh.w), 0.0f);
        }
        return v;
    };

    const float* zr = zin + (size_t)node * DIM;
    float a = 1.0f + eps[l];
    float4 s0 = t4(*(const float4*)(zr + c0),       sc0, sh0);
    float4 s1 = t4(*(const float4*)(zr + 128 + c0), sc1, sh1);
    float4 acc0 = make_float4(a * s0.x, a * s0.y, a * s0.z, a * s0.w);
    float4 acc1 = make_float4(a * s1.x, a * s1.y, a * s1.z, a * s1.w);

    const int beg = g_off[node], end = g_off[node + 1];
    for (int j = beg; j < end; j++) {
        const float* sr = zin + (size_t)g_adj[j] * DIM;
        float4 m0 = t4(*(const float4*)(sr + c0),       sc0, sh0);
        float4 m1 = t4(*(const float4*)(sr + 128 + c0), sc1, sh1);
        if (!TRANSFORM) {
            m0.x = fmaxf(m0.x, 0.f); m0.y = fmaxf(m0.y, 0.f);
            m0.z = fmaxf(m0.z, 0.f); m0.w = fmaxf(m0.w, 0.f);
            m1.x = fmaxf(m1.x, 0.f); m1.y = fmaxf(m1.y, 0.f);
            m1.z = fmaxf(m1.z, 0.f); m1.w = fmaxf(m1.w, 0.f);
        }
        acc0.x += m0.x; acc0.y += m0.y; acc0.z += m0.z; acc0.w += m0.w;
        acc1.x += m1.x; acc1.y += m1.y; acc1.z += m1.z; acc1.w += m1.w;
    }

    float* zo = zout + (size_t)node * DIM;
    *(float4*)(zo + c0)       = acc0;
    *(float4*)(zo + 128 + c0) = acc1;
}

// ---------------- 3xBF16 GEMM, double-buffered, BN-ss prologue ---------------
// (round-12 proven epilogue: shared s_sum/s_sq + global atomics)
template <bool TRANSFORM_A>
__global__ __launch_bounds__(256, 2)
void k_gemm(const float* __restrict__ A, const float* __restrict__ W,
            const float* __restrict__ bias, float* __restrict__ C,
            int slotIn, const float* __restrict__ gamma, const float* __restrict__ beta,
            int slotOut) {
    __shared__ uint32_t As_hi[2][8][SSTRIDE];
    __shared__ uint32_t As_lo[2][8][SSTRIDE];
    __shared__ uint32_t Bs_hi[2][8][SSTRIDE];
    __shared__ uint32_t Bs_lo[2][8][SSTRIDE];
    __shared__ float s_sum[BN];
    __shared__ float s_sq[BN];
    __shared__ float ssm[2 * DIM];

    const int tid  = threadIdx.x;
    const int lane = tid & 31;
    const int warp = tid >> 5;
    const int wr   = warp >> 2;
    const int wc   = warp & 3;
    const int g    = lane >> 2;
    const int t    = lane & 3;

    const int rowBase = blockIdx.y * BM;
    const int colBase = blockIdx.x * BN;

    if (tid < BN) { s_sum[tid] = 0.0f; s_sq[tid] = 0.0f; }
    if (TRANSFORM_A) {
        if (tid < DIM) {
            float sc, sh;
            bn_ss(slotIn, tid, gamma, beta, sc, sh);
            ssm[tid] = sc;
            ssm[DIM + tid] = sh;
        }
        __syncthreads();
    }

    const int arow = tid >> 1;
    const int ak   = (tid & 1) * 4;
    const int bk2  = (tid >> 5) * 2;
    const int bkp  = tid >> 5;
    const int bcol = (tid & 31) * 4;

    const int agrow = rowBase + arow;
    const bool a_ok = (agrow < N_NODES);
    const float* Arow = A + (size_t)agrow * DIM;

    float acc[4][4][4];
#pragma unroll
    for (int mt = 0; mt < 4; mt++)
#pragma unroll
        for (int nt = 0; nt < 4; nt++)
#pragma unroll
            for (int j = 0; j < 4; j++) acc[mt][nt][j] = 0.0f;

    float4 av0, av1, br0, br1;

    auto fetch = [&](int k0) {
        av0 = make_float4(0.f, 0.f, 0.f, 0.f);
        av1 = make_float4(0.f, 0.f, 0.f, 0.f);
        if (a_ok) {
            av0 = *(const float4*)(Arow + k0 + ak);
            av1 = *(const float4*)(Arow + k0 + ak + 8);
        }
        if (TRANSFORM_A) {
            int kc0 = k0 + ak, kc1 = k0 + ak + 8;
            av0.x = fmaxf(fmaf(av0.x, ssm[kc0 + 0], ssm[DIM + kc0 + 0]), 0.0f);
            av0.y = fmaxf(fmaf(av0.y, ssm[kc0 + 1], ssm[DIM + kc0 + 1]), 0.0f);
            av0.z = fmaxf(fmaf(av0.z, ssm[kc0 + 2], ssm[DIM + kc0 + 2]), 0.0f);
            av0.w = fmaxf(fmaf(av0.w, ssm[kc0 + 3], ssm[DIM + kc0 + 3]), 0.0f);
            av1.x = fmaxf(fmaf(av1.x, ssm[kc1 + 0], ssm[DIM + kc1 + 0]), 0.0f);
            av1.y = fmaxf(fmaf(av1.y, ssm[kc1 + 1], ssm[DIM + kc1 + 1]), 0.0f);
            av1.z = fmaxf(fmaf(av1.z, ssm[kc1 + 2], ssm[DIM + kc1 + 2]), 0.0f);
            av1.w = fmaxf(fmaf(av1.w, ssm[kc1 + 3], ssm[DIM + kc1 + 3]), 0.0f);
        }
        br0 = *(const float4*)(W + (size_t)(k0 + bk2)     * DIM + colBase + bcol);
        br1 = *(const float4*)(W + (size_t)(k0 + bk2 + 1) * DIM + colBase + bcol);
    };

    auto stash = [&](int buf) {
        uint32_t hi, lo;
        int kp = ak >> 1;
        split_bf16x2(av0.x, av0.y, hi, lo);
        As_hi[buf][kp][arow] = hi;     As_lo[buf][kp][arow] = lo;
        split_bf16x2(av0.z, av0.w, hi, lo);
        As_hi[buf][kp + 1][arow] = hi; As_lo[buf][kp + 1][arow] = lo;
        split_bf16x2(av1.x, av1.y, hi, lo);
        As_hi[buf][kp + 4][arow] = hi; As_lo[buf][kp + 4][arow] = lo;
        split_bf16x2(av1.z, av1.w, hi, lo);
        As_hi[buf][kp + 5][arow] = hi; As_lo[buf][kp + 5][arow] = lo;
        {
            uint32_t ph[4], pl[4];
            split_bf16x2(br0.x, br1.x, ph[0], pl[0]);
            split_bf16x2(br0.y, br1.y, ph[1], pl[1]);
            split_bf16x2(br0.z, br1.z, ph[2], pl[2]);
            split_bf16x2(br0.w, br1.w, ph[3], pl[3]);
            *(uint4*)&Bs_hi[buf][bkp][bcol] = *(uint4*)ph;
            *(uint4*)&Bs_lo[buf][bkp][bcol] = *(uint4*)pl;
        }
    };

    const int mrow = wr * 64;
    const int ncol = wc * 32;

    fetch(0);
    stash(0);
    __syncthreads();

#pragma unroll 2
    for (int it = 0; it < DIM / BK; it++) {
        const int cur = it & 1;
        if (it < DIM / BK - 1) fetch((it + 1) * BK);

        uint32_t ahi[4][4], bhi[4][2], blo[4][2];
#pragma unroll
        for (int mt = 0; mt < 4; mt++) {
            int r = mrow + mt * 16 + g;
            ahi[mt][0] = As_hi[cur][t][r];
            ahi[mt][1] = As_hi[cur][t][r + 8];
            ahi[mt][2] = As_hi[cur][t + 4][r];
            ahi[mt][3] = As_hi[cur][t + 4][r + 8];
        }
#pragma unroll
        for (int nt = 0; nt < 4; nt++) {
            int c = ncol + nt * 8 + g;
            bhi[nt][0] = Bs_hi[cur][t][c];
            bhi[nt][1] = Bs_hi[cur][t + 4][c];
            blo[nt][0] = Bs_lo[cur][t][c];
            blo[nt][1] = Bs_lo[cur][t + 4][c];
        }
#pragma unroll
        for (int mt = 0; mt < 4; mt++)
#pragma unroll
            for (int nt = 0; nt < 4; nt++)
                mma_bf16(acc[mt][nt], ahi[mt], bhi[nt]);
#pragma unroll
        for (int mt = 0; mt < 4; mt++)
#pragma unroll
            for (int nt = 0; nt < 4; nt++)
                mma_bf16(acc[mt][nt], ahi[mt], blo[nt]);
        uint32_t alo[4][4];
#pragma unroll
        for (int mt = 0; mt < 4; mt++) {
            int r = mrow + mt * 16 + g;
            alo[mt][0] = As_lo[cur][t][r];
            alo[mt][1] = As_lo[cur][t][r + 8];
            alo[mt][2] = As_lo[cur][t + 4][r];
            alo[mt][3] = As_lo[cur][t + 4][r + 8];
        }
#pragma unroll
        for (int mt = 0; mt < 4; mt++)
#pragma unroll
            for (int nt = 0; nt < 4; nt++)
                mma_bf16(acc[mt][nt], alo[mt], bhi[nt]);

        if (it < DIM / BK - 1) {
            stash(cur ^ 1);
            __syncthreads();
        }
    }

    // ---- epilogue: bias, store, per-column BN stats ----
    float bs[4][2];
#pragma unroll
    for (int nt = 0; nt < 4; nt++) {
        int c = colBase + ncol + nt * 8 + 2 * t;
        bs[nt][0] = bias[c];
        bs[nt][1] = bias[c + 1];
    }

    float csum[4][2], csq[4][2];
#pragma unroll
    for (int nt = 0; nt < 4; nt++) {
        csum[nt][0] = 0.f; csum[nt][1] = 0.f;
        csq[nt][0] = 0.f;  csq[nt][1] = 0.f;
    }

#pragma unroll
    for (int mt = 0; mt < 4; mt++) {
        int r0 = rowBase + mrow + mt * 16 + g;
        int r1 = r0 + 8;
        bool ok0 = (r0 < N_NODES), ok1 = (r1 < N_NODES);
#pragma unroll
        for (int nt = 0; nt < 4; nt++) {
            int c = colBase + ncol + nt * 8 + 2 * t;
            float v0 = acc[mt][nt][0] + bs[nt][0];
            float v1 = acc[mt][nt][1] + bs[nt][1];
            float v2 = acc[mt][nt][2] + bs[nt][0];
            float v3 = acc[mt][nt][3] + bs[nt][1];
            if (ok0) {
                *(float2*)(C + (size_t)r0 * DIM + c) = make_float2(v0, v1);
                csum[nt][0] += v0; csq[nt][0] += v0 * v0;
                csum[nt][1] += v1; csq[nt][1] += v1 * v1;
            }
            if (ok1) {
                *(float2*)(C + (size_t)r1 * DIM + c) = make_float2(v2, v3);
                csum[nt][0] += v2; csq[nt][0] += v2 * v2;
                csum[nt][1] += v3; csq[nt][1] += v3 * v3;
            }
        }
    }
#pragma unroll
    for (int nt = 0; nt < 4; nt++) {
        int lc = ncol + nt * 8 + 2 * t;
        atomicAdd(&s_sum[lc],     csum[nt][0]);
        atomicAdd(&s_sq[lc],      csq[nt][0]);
        atomicAdd(&s_sum[lc + 1], csum[nt][1]);
        atomicAdd(&s_sq[lc + 1],  csq[nt][1]);
    }
    __syncthreads();
    if (tid < BN) {
        atomicAdd(&g_stats[slotOut * 512 +       colBase + tid], s_sum[tid]);
        atomicAdd(&g_stats[slotOut * 512 + 256 + colBase + tid], s_sq[tid]);
    }
}

// last layer's BN2 -> g_ss2 for k_out
__global__ void k_finalize(int slot, const float* __restrict__ gamma,
                           const float* __restrict__ beta) {
    int c = threadIdx.x;
    if (c >= DIM) return;
    float sc, sh;
    bn_ss(slot, c, gamma, beta, sc, sh);
    g_ss2[c]       = sc;
    g_ss2[DIM + c] = sh;
}

// final output: out = ss2 * v + shift  (no relu, layer L-1)
__global__ void k_out(const float* __restrict__ vin, float* __restrict__ out) {
    long i = (long)blockIdx.x * 256 + threadIdx.x;
    const long tot = (long)N_NODES * DIM / 4;
    if (i >= tot) return;
    int c = (int)(i & 63) << 2;
    float4 v = ((const float4*)vin)[i];
    v.x = fmaf(v.x, g_ss2[c + 0], g_ss2[DIM + c + 0]);
    v.y = fmaf(v.y, g_ss2[c + 1], g_ss2[DIM + c + 1]);
    v.z = fmaf(v.z, g_ss2[c + 2], g_ss2[DIM + c + 2]);
    v.w = fmaf(v.w, g_ss2[c + 3], g_ss2[DIM + c + 3]);
    ((float4*)out)[i] = v;
}

// ---------------- host-side orchestration ------------------------------------
extern "C" void kernel_launch(void* const* d_in, const int* in_sizes, int n_in,
                              void* d_out, int out_size) {
    const float* x    = (const float*)d_in[0];
    const int*   src  = (const int*)  d_in[1];
    const int*   dst  = (const int*)  d_in[2];
    const float* W1   = (const float*)d_in[3];
    const float* b1   = (const float*)d_in[4];
    const float* g1   = (const float*)d_in[5];
    const float* bt1  = (const float*)d_in[6];
    const float* W2   = (const float*)d_in[7];
    const float* b2   = (const float*)d_in[8];
    const float* eps  = (const float*)d_in[9];
    const float* bn_g = (const float*)d_in[10];
    const float* bn_b = (const float*)d_in[11];
    float* out = (float*)d_out;

    float *zp, *yp, *vp;
    cudaGetSymbolAddress((void**)&zp, g_z);
    cudaGetSymbolAddress((void**)&yp, g_y);
    cudaGetSymbolAddress((void**)&vp, g_v);

    const long ew_items = (long)N_NODES * DIM / 4;
    const int  ew_grid  = (int)((ew_items + 255) / 256);
    const dim3 gemm_grid(DIM / BN, (N_NODES + BM - 1) / BM);   // (2, 391)
    const int  gat_grid = (N_NODES + 7) / 8;                   // 6250

    // ---- init + CSR build (once per launch) ----
    k_zero_init<<<(N_NODES + 255) / 256, 256>>>();
    k_hist<<<(NE + 255) / 256, 256>>>(dst);
    k_scan1<<<NBLK_SCAN, 1024>>>();
    k_scan3<<<NBLK_SCAN, 1024>>>();
    k_fill<<<(NE + 255) / 256, 256>>>(src, dst);

    for (int l = 0; l < NL; l++) {
        if (l == 0)
            k_gather<false><<<gat_grid, 256>>>(x, zp, eps, 0, 0, nullptr, nullptr);
        else
            k_gather<true><<<gat_grid, 256>>>(vp, zp, eps, l,
                                              (l - 1) * 2 + 1,
                                              bn_g + (size_t)(l - 1) * DIM,
                                              bn_b + (size_t)(l - 1) * DIM);

        k_gemm<false><<<gemm_grid, 256>>>(zp, W1 + (size_t)l * DIM * DIM,
                                          b1 + (size_t)l * DIM, yp,
                                          0, nullptr, nullptr, l * 2);

        k_gemm<true><<<gemm_grid, 256>>>(yp, W2 + (size_t)l * DIM * DIM,
                                         b2 + (size_t)l * DIM, vp,
                                         l * 2,
                                         g1 + (size_t)l * DIM,
                                         bt1 + (size_t)l * DIM,
                                         l * 2 + 1);
    }

    k_finalize<<<1, 256>>>((NL - 1) * 2 + 1,
                           bn_g + (size_t)(NL - 1) * DIM,
                           bn_b + (size_t)(NL - 1) * DIM);
    k_out<<<ew_grid, 256>>>(vp, out);
}